// round 3
// baseline (speedup 1.0000x reference)
#include <cuda_runtime.h>
#include <math.h>

// ---------------------------------------------------------------------------
// Problem constants (match reference)
// ---------------------------------------------------------------------------
#define NUSER 100000
#define NITEM 200000
#define NALL  300000
#define HID   128
#define EUI   2000000
#define EUU   800000
#define LUI   3
#define LUU   2

// ---------------------------------------------------------------------------
// Scratch (device globals — no allocation allowed)
// ---------------------------------------------------------------------------
__device__ float g_emb  [(size_t)NALL * HID];   // current layer embeddings
__device__ float g_nodef[(size_t)NALL * HID];   // GEMM output / SpMM input

__device__ int   g_rp_ui [NALL + 1];
__device__ int   g_cur_ui[NALL];
__device__ int   g_col_ui[EUI];
__device__ int   g_rp_uu [NUSER + 1];
__device__ int   g_cur_uu[NUSER];
__device__ int   g_col_uu[EUU];

__device__ int   g_do_ui[NALL];
__device__ int   g_di_ui[NALL];
__device__ int   g_do_uu[NUSER];
__device__ int   g_di_uu[NUSER];

__device__ float g_os_ui[NALL];
__device__ float g_is_ui[NALL];
__device__ float g_os_uu[NUSER];
__device__ float g_is_uu[NUSER];

__device__ int   g_bsum[512];

// ---------------------------------------------------------------------------
// Graph preprocessing kernels
// ---------------------------------------------------------------------------
__global__ void k_hist(const int* __restrict__ src, const int* __restrict__ dst,
                       int E, int* __restrict__ dsrc, int* __restrict__ ddst) {
    int i = blockIdx.x * blockDim.x + threadIdx.x;
    if (i < E) {
        atomicAdd(&dsrc[src[i]], 1);
        atomicAdd(&ddst[dst[i]], 1);
    }
}

// Exclusive scan, block-local (1024 elems/block). Scans n+1 virtual elements
// (value 0 beyond n) so out[] gets the full row_ptr including the total.
__global__ void k_scan_block(const int* __restrict__ deg, int n,
                             int* __restrict__ out, int* __restrict__ bsum) {
    __shared__ int s[1024];
    int tid = threadIdx.x;
    int i = blockIdx.x * 1024 + tid;
    int v = (i < n) ? deg[i] : 0;
    s[tid] = v;
    __syncthreads();
    for (int off = 1; off < 1024; off <<= 1) {
        int t = (tid >= off) ? s[tid - off] : 0;
        __syncthreads();
        s[tid] += t;
        __syncthreads();
    }
    if (i <= n) out[i] = s[tid] - v;          // exclusive
    if (tid == 1023) bsum[blockIdx.x] = s[1023];
}

__global__ void k_scan_sums(int* __restrict__ bs, int nb) {
    __shared__ int s[512];
    int tid = threadIdx.x;
    int v = (tid < nb) ? bs[tid] : 0;
    s[tid] = v;
    __syncthreads();
    for (int off = 1; off < 512; off <<= 1) {
        int t = (tid >= off) ? s[tid - off] : 0;
        __syncthreads();
        s[tid] += t;
        __syncthreads();
    }
    if (tid < nb) bs[tid] = s[tid] - v;       // exclusive
}

__global__ void k_add(int* __restrict__ rp, int* __restrict__ cur,
                      const int* __restrict__ bs, int total) {
    int i = blockIdx.x * blockDim.x + threadIdx.x;
    if (i < total) {
        int v = rp[i] + bs[i >> 10];
        rp[i] = v;
        if (i < total - 1) cur[i] = v;        // cursor copy for scatter
    }
}

__global__ void k_scales(const int* __restrict__ dout, const int* __restrict__ din,
                         float* __restrict__ os, float* __restrict__ is_, int n) {
    int i = blockIdx.x * blockDim.x + threadIdx.x;
    if (i < n) {
        os[i]  = rsqrtf(fmaxf((float)dout[i], 1.0f));
        is_[i] = rsqrtf(fmaxf((float)din[i],  1.0f));
    }
}

__global__ void k_scatter(const int* __restrict__ src, const int* __restrict__ dst,
                          int E, int* __restrict__ cur, int* __restrict__ col) {
    int i = blockIdx.x * blockDim.x + threadIdx.x;
    if (i < E) {
        int pos = atomicAdd(&cur[dst[i]], 1);
        col[pos] = src[i];
    }
}

// Make per-row neighbor order deterministic (atomic scatter order varies per
// replay; sorting the multiset fixes the summation order bit-exactly).
__global__ void k_sortrows(const int* __restrict__ rp, int* __restrict__ col, int n) {
    int i = blockIdx.x * blockDim.x + threadIdx.x;
    if (i >= n) return;
    int b = rp[i], e = rp[i + 1];
    for (int j = b + 1; j < e; j++) {
        int key = col[j];
        int k = j - 1;
        while (k >= b && col[k] > key) { col[k + 1] = col[k]; k--; }
        col[k + 1] = key;
    }
}

__global__ void k_copy4(float* __restrict__ dst, const float* __restrict__ src, int n4) {
    int i = blockIdx.x * blockDim.x + threadIdx.x;
    if (i < n4)
        reinterpret_cast<float4*>(dst)[i] = reinterpret_cast<const float4*>(src)[i];
}

// ---------------------------------------------------------------------------
// GEMM: C[r,:] = (A[r,:] @ W) * oscale[r], A:[M,128], W:[128,128] row-major.
// 128x128 block tile, BK=16, 256 threads, 8x8 micro-tile per thread.
// ---------------------------------------------------------------------------
__global__ __launch_bounds__(256)
void k_gemm(const float* __restrict__ A, const float* __restrict__ W,
            const float* __restrict__ oscale, float* __restrict__ C, int M) {
    __shared__ float As[16][128];   // [k][m]
    __shared__ float Bs[16][128];   // [k][n]
    const int tid = threadIdx.x;
    const int tx = tid & 15;        // col group
    const int ty = tid >> 4;        // row group
    const int row0 = blockIdx.x * 128;

    float acc[8][8];
#pragma unroll
    for (int i = 0; i < 8; i++)
#pragma unroll
        for (int j = 0; j < 8; j++) acc[i][j] = 0.0f;

    for (int k0 = 0; k0 < 128; k0 += 16) {
#pragma unroll
        for (int q = 0; q < 2; q++) {
            int idx = tid + q * 256;
            // A tile: 128 rows x 16 k -> 512 float4 (4 per row)
            int ar = idx >> 2, ac4 = idx & 3;
            float4 v = make_float4(0.f, 0.f, 0.f, 0.f);
            int gr = row0 + ar;
            if (gr < M)
                v = *reinterpret_cast<const float4*>(A + (size_t)gr * 128 + k0 + ac4 * 4);
            As[ac4 * 4 + 0][ar] = v.x;
            As[ac4 * 4 + 1][ar] = v.y;
            As[ac4 * 4 + 2][ar] = v.z;
            As[ac4 * 4 + 3][ar] = v.w;
            // W tile: 16 k-rows x 128 cols -> 512 float4 (32 per row)
            int wk = idx >> 5, wc4 = idx & 31;
            *reinterpret_cast<float4*>(&Bs[wk][wc4 * 4]) =
                *reinterpret_cast<const float4*>(W + (size_t)(k0 + wk) * 128 + wc4 * 4);
        }
        __syncthreads();
#pragma unroll
        for (int k = 0; k < 16; k++) {
            float a[8], b[8];
            *reinterpret_cast<float4*>(&a[0]) = *reinterpret_cast<const float4*>(&As[k][ty * 8]);
            *reinterpret_cast<float4*>(&a[4]) = *reinterpret_cast<const float4*>(&As[k][ty * 8 + 4]);
            *reinterpret_cast<float4*>(&b[0]) = *reinterpret_cast<const float4*>(&Bs[k][tx * 8]);
            *reinterpret_cast<float4*>(&b[4]) = *reinterpret_cast<const float4*>(&Bs[k][tx * 8 + 4]);
#pragma unroll
            for (int i = 0; i < 8; i++)
#pragma unroll
                for (int j = 0; j < 8; j++)
                    acc[i][j] = fmaf(a[i], b[j], acc[i][j]);
        }
        __syncthreads();
    }

#pragma unroll
    for (int i = 0; i < 8; i++) {
        int r = row0 + ty * 8 + i;
        if (r < M) {
            float s = oscale[r];
            float4 o0 = make_float4(acc[i][0] * s, acc[i][1] * s, acc[i][2] * s, acc[i][3] * s);
            float4 o1 = make_float4(acc[i][4] * s, acc[i][5] * s, acc[i][6] * s, acc[i][7] * s);
            float* cp = C + (size_t)r * 128 + tx * 8;
            *reinterpret_cast<float4*>(cp)     = o0;
            *reinterpret_cast<float4*>(cp + 4) = o1;
        }
    }
}

// ---------------------------------------------------------------------------
// CSR SpMM + fused epilogue. One warp per destination row:
//   agg = sum_{s in neigh(d)} nodef[s,:]   (nodef already out-degree scaled)
//   rst = leaky_relu(agg * in_scale[d], 0.5)
//   emb[d,:] = rst
//   acc_out[d,:] += rst / max(||rst||2, 1e-12)
// ---------------------------------------------------------------------------
__global__ __launch_bounds__(256)
void k_spmm(const float* __restrict__ nodef, const int* __restrict__ rp,
            const int* __restrict__ col, const float* __restrict__ isc,
            float* __restrict__ emb, float* __restrict__ acc_out, int n) {
    int w = (blockIdx.x * blockDim.x + threadIdx.x) >> 5;
    int lane = threadIdx.x & 31;
    if (w >= n) return;
    int b = rp[w], e = rp[w + 1];

    float4 a = make_float4(0.f, 0.f, 0.f, 0.f);
    int j = b;
    for (; j + 4 <= e; j += 4) {
        int s0 = col[j], s1 = col[j + 1], s2 = col[j + 2], s3 = col[j + 3];
        float4 v0 = __ldg(reinterpret_cast<const float4*>(nodef + (size_t)s0 * HID) + lane);
        float4 v1 = __ldg(reinterpret_cast<const float4*>(nodef + (size_t)s1 * HID) + lane);
        float4 v2 = __ldg(reinterpret_cast<const float4*>(nodef + (size_t)s2 * HID) + lane);
        float4 v3 = __ldg(reinterpret_cast<const float4*>(nodef + (size_t)s3 * HID) + lane);
        a.x += v0.x + v1.x + v2.x + v3.x;
        a.y += v0.y + v1.y + v2.y + v3.y;
        a.z += v0.z + v1.z + v2.z + v3.z;
        a.w += v0.w + v1.w + v2.w + v3.w;
    }
    for (; j < e; j++) {
        int s = col[j];
        float4 v = __ldg(reinterpret_cast<const float4*>(nodef + (size_t)s * HID) + lane);
        a.x += v.x; a.y += v.y; a.z += v.z; a.w += v.w;
    }

    float sc = isc[w];
    a.x *= sc; a.y *= sc; a.z *= sc; a.w *= sc;
    // leaky_relu(x, 0.5)
    a.x = a.x >= 0.f ? a.x : 0.5f * a.x;
    a.y = a.y >= 0.f ? a.y : 0.5f * a.y;
    a.z = a.z >= 0.f ? a.z : 0.5f * a.z;
    a.w = a.w >= 0.f ? a.w : 0.5f * a.w;

    reinterpret_cast<float4*>(emb + (size_t)w * HID)[lane] = a;

    float sq = a.x * a.x + a.y * a.y + a.z * a.z + a.w * a.w;
#pragma unroll
    for (int o = 16; o > 0; o >>= 1)
        sq += __shfl_xor_sync(0xffffffffu, sq, o);
    float inv = 1.0f / fmaxf(sqrtf(sq), 1e-12f);

    float4* op = reinterpret_cast<float4*>(acc_out + (size_t)w * HID) + lane;
    float4 o = *op;
    o.x += a.x * inv; o.y += a.y * inv; o.z += a.z * inv; o.w += a.w * inv;
    *op = o;
}

// ---------------------------------------------------------------------------
// Launch
// ---------------------------------------------------------------------------
extern "C" void kernel_launch(void* const* d_in, const int* in_sizes, int n_in,
                              void* d_out, int out_size) {
    (void)in_sizes; (void)n_in; (void)out_size;
    const float* user_emb = (const float*)d_in[0];
    const float* item_emb = (const float*)d_in[1];
    const float* ui_u_w   = (const float*)d_in[2];
    const float* ui_v_w   = (const float*)d_in[3];
    const float* uu_u_w   = (const float*)d_in[4];
    const int*   src_ui   = (const int*)d_in[5];
    const int*   dst_ui   = (const int*)d_in[6];
    const int*   src_uu   = (const int*)d_in[7];
    const int*   dst_uu   = (const int*)d_in[8];
    float* out = (float*)d_out;

    void* p;
    float *emb, *nodef, *os_ui, *is_ui, *os_uu, *is_uu;
    int *rp_ui, *cur_ui, *col_ui, *rp_uu, *cur_uu, *col_uu;
    int *do_ui, *di_ui, *do_uu, *di_uu, *bsum;
    cudaGetSymbolAddress(&p, g_emb);    emb    = (float*)p;
    cudaGetSymbolAddress(&p, g_nodef);  nodef  = (float*)p;
    cudaGetSymbolAddress(&p, g_os_ui);  os_ui  = (float*)p;
    cudaGetSymbolAddress(&p, g_is_ui);  is_ui  = (float*)p;
    cudaGetSymbolAddress(&p, g_os_uu);  os_uu  = (float*)p;
    cudaGetSymbolAddress(&p, g_is_uu);  is_uu  = (float*)p;
    cudaGetSymbolAddress(&p, g_rp_ui);  rp_ui  = (int*)p;
    cudaGetSymbolAddress(&p, g_cur_ui); cur_ui = (int*)p;
    cudaGetSymbolAddress(&p, g_col_ui); col_ui = (int*)p;
    cudaGetSymbolAddress(&p, g_rp_uu);  rp_uu  = (int*)p;
    cudaGetSymbolAddress(&p, g_cur_uu); cur_uu = (int*)p;
    cudaGetSymbolAddress(&p, g_col_uu); col_uu = (int*)p;
    cudaGetSymbolAddress(&p, g_do_ui);  do_ui  = (int*)p;
    cudaGetSymbolAddress(&p, g_di_ui);  di_ui  = (int*)p;
    cudaGetSymbolAddress(&p, g_do_uu);  do_uu  = (int*)p;
    cudaGetSymbolAddress(&p, g_di_uu);  di_uu  = (int*)p;
    cudaGetSymbolAddress(&p, g_bsum);   bsum   = (int*)p;

    cudaStream_t st = 0;

    // ---- degrees ----
    cudaMemsetAsync(do_ui, 0, NALL  * sizeof(int), st);
    cudaMemsetAsync(di_ui, 0, NALL  * sizeof(int), st);
    cudaMemsetAsync(do_uu, 0, NUSER * sizeof(int), st);
    cudaMemsetAsync(di_uu, 0, NUSER * sizeof(int), st);
    k_hist<<<(EUI + 255) / 256, 256, 0, st>>>(src_ui, dst_ui, EUI, do_ui, di_ui);
    k_hist<<<(EUU + 255) / 256, 256, 0, st>>>(src_uu, dst_uu, EUU, do_uu, di_uu);

    // ---- row_ptr (exclusive scan of in-degree) : ui ----
    {
        int nb = (NALL + 1 + 1023) / 1024;
        k_scan_block<<<nb, 1024, 0, st>>>(di_ui, NALL, rp_ui, bsum);
        k_scan_sums<<<1, 512, 0, st>>>(bsum, nb);
        k_add<<<(NALL + 1 + 255) / 256, 256, 0, st>>>(rp_ui, cur_ui, bsum, NALL + 1);
    }
    // ---- row_ptr : uu ----
    {
        int nb = (NUSER + 1 + 1023) / 1024;
        k_scan_block<<<nb, 1024, 0, st>>>(di_uu, NUSER, rp_uu, bsum);
        k_scan_sums<<<1, 512, 0, st>>>(bsum, nb);
        k_add<<<(NUSER + 1 + 255) / 256, 256, 0, st>>>(rp_uu, cur_uu, bsum, NUSER + 1);
    }

    k_scales<<<(NALL  + 255) / 256, 256, 0, st>>>(do_ui, di_ui, os_ui, is_ui, NALL);
    k_scales<<<(NUSER + 255) / 256, 256, 0, st>>>(do_uu, di_uu, os_uu, is_uu, NUSER);

    k_scatter<<<(EUI + 255) / 256, 256, 0, st>>>(src_ui, dst_ui, EUI, cur_ui, col_ui);
    k_scatter<<<(EUU + 255) / 256, 256, 0, st>>>(src_uu, dst_uu, EUU, cur_uu, col_uu);
    k_sortrows<<<(NALL  + 255) / 256, 256, 0, st>>>(rp_ui, col_ui, NALL);
    k_sortrows<<<(NUSER + 255) / 256, 256, 0, st>>>(rp_uu, col_uu, NUSER);

    // ---- init embeddings + output accumulators ----
    const int U4 = NUSER * HID / 4;   // 3.2M float4
    const int I4 = NITEM * HID / 4;   // 6.4M float4
    k_copy4<<<(U4 + 255) / 256, 256, 0, st>>>(emb, user_emb, U4);
    k_copy4<<<(I4 + 255) / 256, 256, 0, st>>>(emb + (size_t)NUSER * HID, item_emb, I4);
    k_copy4<<<(U4 + 255) / 256, 256, 0, st>>>(out, user_emb, U4);
    k_copy4<<<(I4 + 255) / 256, 256, 0, st>>>(out + (size_t)NUSER * HID, item_emb, I4);
    k_copy4<<<(U4 + 255) / 256, 256, 0, st>>>(out + (size_t)NALL * HID, user_emb, U4);

    // ---- user-item propagation (3 layers) ----
    for (int i = 0; i < LUI; i++) {
        k_gemm<<<(NUSER + 127) / 128, 256, 0, st>>>(
            emb, ui_u_w + (size_t)i * HID * HID, os_ui, nodef, NUSER);
        k_gemm<<<(NITEM + 127) / 128, 256, 0, st>>>(
            emb + (size_t)NUSER * HID, ui_v_w + (size_t)i * HID * HID,
            os_ui + NUSER, nodef + (size_t)NUSER * HID, NITEM);
        k_spmm<<<(NALL + 7) / 8, 256, 0, st>>>(
            nodef, rp_ui, col_ui, is_ui, emb, out, NALL);
    }

    // ---- user-user (social) propagation (2 layers) ----
    k_copy4<<<(U4 + 255) / 256, 256, 0, st>>>(emb, user_emb, U4);
    for (int i = 0; i < LUU; i++) {
        k_gemm<<<(NUSER + 127) / 128, 256, 0, st>>>(
            emb, uu_u_w + (size_t)i * HID * HID, os_uu, nodef, NUSER);
        k_spmm<<<(NUSER + 7) / 8, 256, 0, st>>>(
            nodef, rp_uu, col_uu, is_uu, emb, out + (size_t)NALL * HID, NUSER);
    }
}

// round 5
// speedup vs baseline: 1.3827x; 1.3827x over previous
#include <cuda_runtime.h>
#include <cuda_bf16.h>
#include <cstdint>
#include <stdint.h>
#include <math.h>

// ---------------------------------------------------------------------------
// Problem constants
// ---------------------------------------------------------------------------
#define NUSER 100000
#define NITEM 200000
#define NALL  300000
#define HID   128
#define EUI   2000000
#define EUU   800000
#define LUI   3
#define LUU   2

#define APITCH 136              // bf16 elements per SMEM row (272B: conflict-free ldmatrix)
#define GEMM_SMEM (4 * 128 * APITCH * 2)   // Ah, Al, Wh, Wl  (139264 B)

// ---------------------------------------------------------------------------
// Scratch (device globals — no allocation allowed)
// ---------------------------------------------------------------------------
__device__ float g_emb  [(size_t)NALL * HID];
__device__ float g_nodef[(size_t)NALL * HID];

__device__ int   g_rp_ui [NALL + 1];
__device__ int   g_cur_ui[NALL];
__device__ int   g_col_ui[EUI];
__device__ int   g_rp_uu [NUSER + 1];
__device__ int   g_cur_uu[NUSER];
__device__ int   g_col_uu[EUU];

__device__ int   g_do_ui[NALL];
__device__ int   g_di_ui[NALL];
__device__ int   g_do_uu[NUSER];
__device__ int   g_di_uu[NUSER];

__device__ float g_os_ui[NALL];
__device__ float g_is_ui[NALL];
__device__ float g_os_uu[NUSER];
__device__ float g_is_uu[NUSER];

__device__ int   g_bsum[512];

// ---------------------------------------------------------------------------
// Preprocessing kernels
// ---------------------------------------------------------------------------
__global__ void k_hist(const int* __restrict__ src, const int* __restrict__ dst,
                       int E, int* __restrict__ dsrc, int* __restrict__ ddst) {
    int i = blockIdx.x * blockDim.x + threadIdx.x;
    if (i < E) {
        atomicAdd(&dsrc[src[i]], 1);
        atomicAdd(&ddst[dst[i]], 1);
    }
}

__global__ void k_scan_block(const int* __restrict__ deg, int n,
                             int* __restrict__ out, int* __restrict__ bsum) {
    __shared__ int s[1024];
    int tid = threadIdx.x;
    int i = blockIdx.x * 1024 + tid;
    int v = (i < n) ? deg[i] : 0;
    s[tid] = v;
    __syncthreads();
    for (int off = 1; off < 1024; off <<= 1) {
        int t = (tid >= off) ? s[tid - off] : 0;
        __syncthreads();
        s[tid] += t;
        __syncthreads();
    }
    if (i <= n) out[i] = s[tid] - v;
    if (tid == 1023) bsum[blockIdx.x] = s[1023];
}

__global__ void k_scan_sums(int* __restrict__ bs, int nb) {
    __shared__ int s[512];
    int tid = threadIdx.x;
    int v = (tid < nb) ? bs[tid] : 0;
    s[tid] = v;
    __syncthreads();
    for (int off = 1; off < 512; off <<= 1) {
        int t = (tid >= off) ? s[tid - off] : 0;
        __syncthreads();
        s[tid] += t;
        __syncthreads();
    }
    if (tid < nb) bs[tid] = s[tid] - v;
}

__global__ void k_add(int* __restrict__ rp, int* __restrict__ cur,
                      const int* __restrict__ bs, int total) {
    int i = blockIdx.x * blockDim.x + threadIdx.x;
    if (i < total) {
        int v = rp[i] + bs[i >> 10];
        rp[i] = v;
        if (i < total - 1) cur[i] = v;
    }
}

__global__ void k_scales(const int* __restrict__ dout, const int* __restrict__ din,
                         float* __restrict__ os, float* __restrict__ is_, int n) {
    int i = blockIdx.x * blockDim.x + threadIdx.x;
    if (i < n) {
        os[i]  = rsqrtf(fmaxf((float)dout[i], 1.0f));
        is_[i] = rsqrtf(fmaxf((float)din[i],  1.0f));
    }
}

__global__ void k_scatter(const int* __restrict__ src, const int* __restrict__ dst,
                          int E, int* __restrict__ cur, int* __restrict__ col) {
    int i = blockIdx.x * blockDim.x + threadIdx.x;
    if (i < E) {
        int pos = atomicAdd(&cur[dst[i]], 1);
        col[pos] = src[i];
    }
}

__global__ void k_sortrows(const int* __restrict__ rp, int* __restrict__ col, int n) {
    int i = blockIdx.x * blockDim.x + threadIdx.x;
    if (i >= n) return;
    int b = rp[i], e = rp[i + 1];
    for (int j = b + 1; j < e; j++) {
        int key = col[j];
        int k = j - 1;
        while (k >= b && col[k] > key) { col[k + 1] = col[k]; k--; }
        col[k + 1] = key;
    }
}

__global__ void k_copy4(float* __restrict__ dst, const float* __restrict__ src, int n4) {
    int i = blockIdx.x * blockDim.x + threadIdx.x;
    if (i < n4)
        reinterpret_cast<float4*>(dst)[i] = reinterpret_cast<const float4*>(src)[i];
}

// ---------------------------------------------------------------------------
// Tensor-core GEMM: C = A @ W  (A:[M,128] fp32, W:[128,128] fp32 row-major)
// bf16 2-term split (Ah*Wh + Al*Wh + Ah*Wl) via mma.sync.m16n8k16.
// One block = 128 rows x 128 cols, K=128 in a single SMEM slab.
// ---------------------------------------------------------------------------
__device__ __forceinline__ void cvt_split4(float4 v,
        __nv_bfloat162& h01, __nv_bfloat162& h23,
        __nv_bfloat162& l01, __nv_bfloat162& l23) {
    __nv_bfloat16 hx = __float2bfloat16_rn(v.x);
    __nv_bfloat16 hy = __float2bfloat16_rn(v.y);
    __nv_bfloat16 hz = __float2bfloat16_rn(v.z);
    __nv_bfloat16 hw = __float2bfloat16_rn(v.w);
    __nv_bfloat16 lx = __float2bfloat16_rn(v.x - __bfloat162float(hx));
    __nv_bfloat16 ly = __float2bfloat16_rn(v.y - __bfloat162float(hy));
    __nv_bfloat16 lz = __float2bfloat16_rn(v.z - __bfloat162float(hz));
    __nv_bfloat16 lw = __float2bfloat16_rn(v.w - __bfloat162float(hw));
    h01 = __nv_bfloat162(hx, hy); h23 = __nv_bfloat162(hz, hw);
    l01 = __nv_bfloat162(lx, ly); l23 = __nv_bfloat162(lz, lw);
}

__device__ __forceinline__ unsigned int smem_u32(const void* p) {
    return (unsigned int)__cvta_generic_to_shared(p);
}

__device__ __forceinline__ void ldsm_x4(unsigned int addr,
        unsigned int& r0, unsigned int& r1, unsigned int& r2, unsigned int& r3) {
    asm volatile("ldmatrix.sync.aligned.m8n8.x4.shared.b16 {%0,%1,%2,%3}, [%4];"
                 : "=r"(r0), "=r"(r1), "=r"(r2), "=r"(r3) : "r"(addr));
}
__device__ __forceinline__ void ldsm_x4t(unsigned int addr,
        unsigned int& r0, unsigned int& r1, unsigned int& r2, unsigned int& r3) {
    asm volatile("ldmatrix.sync.aligned.m8n8.x4.trans.shared.b16 {%0,%1,%2,%3}, [%4];"
                 : "=r"(r0), "=r"(r1), "=r"(r2), "=r"(r3) : "r"(addr));
}
__device__ __forceinline__ void mma16816(float* c,
        unsigned int a0, unsigned int a1, unsigned int a2, unsigned int a3,
        unsigned int b0, unsigned int b1) {
    asm volatile("mma.sync.aligned.m16n8k16.row.col.f32.bf16.bf16.f32 "
                 "{%0,%1,%2,%3}, {%4,%5,%6,%7}, {%8,%9}, {%0,%1,%2,%3};"
                 : "+f"(c[0]), "+f"(c[1]), "+f"(c[2]), "+f"(c[3])
                 : "r"(a0), "r"(a1), "r"(a2), "r"(a3), "r"(b0), "r"(b1));
}

__global__ __launch_bounds__(256)
void k_gemm(const float* __restrict__ A, const float* __restrict__ W,
            float* __restrict__ C, int M) {
    extern __shared__ __align__(16) unsigned char smem[];
    __nv_bfloat16* Ah = reinterpret_cast<__nv_bfloat16*>(smem);
    __nv_bfloat16* Al = Ah + 128 * APITCH;
    __nv_bfloat16* Wh = Al + 128 * APITCH;
    __nv_bfloat16* Wl = Wh + 128 * APITCH;

    const int tid = threadIdx.x;
    const int row0 = blockIdx.x * 128;

    // ---- stage A and W into SMEM as bf16 hi/lo (fused conversion) ----
#pragma unroll
    for (int i = 0; i < 16; i++) {
        int idx = tid + i * 256;           // 4096 float4 per matrix
        int r  = idx >> 5;                 // row (A) / k (W)
        int c4 = idx & 31;                 // float4 within row
        // A
        float4 va = make_float4(0.f, 0.f, 0.f, 0.f);
        if (row0 + r < M)
            va = *reinterpret_cast<const float4*>(A + (size_t)(row0 + r) * 128 + c4 * 4);
        __nv_bfloat162 h01, h23, l01, l23;
        cvt_split4(va, h01, h23, l01, l23);
        __nv_bfloat162* pa = reinterpret_cast<__nv_bfloat162*>(Ah + r * APITCH + c4 * 4);
        pa[0] = h01; pa[1] = h23;
        __nv_bfloat162* pal = reinterpret_cast<__nv_bfloat162*>(Al + r * APITCH + c4 * 4);
        pal[0] = l01; pal[1] = l23;
        // W (same indexing: row = k)
        float4 vw = *reinterpret_cast<const float4*>(W + (size_t)r * 128 + c4 * 4);
        cvt_split4(vw, h01, h23, l01, l23);
        __nv_bfloat162* pw = reinterpret_cast<__nv_bfloat162*>(Wh + r * APITCH + c4 * 4);
        pw[0] = h01; pw[1] = h23;
        __nv_bfloat162* pwl = reinterpret_cast<__nv_bfloat162*>(Wl + r * APITCH + c4 * 4);
        pwl[0] = l01; pwl[1] = l23;
    }
    __syncthreads();

    // ---- compute: warp w owns rows m0..m0+15, full N=128 ----
    const int lane = tid & 31;
    const int w    = tid >> 5;
    const int m0   = w * 16;

    float acc[16][4];
#pragma unroll
    for (int i = 0; i < 16; i++)
#pragma unroll
        for (int j = 0; j < 4; j++) acc[i][j] = 0.0f;

    // A ldmatrix lane addressing (x4): row = m0 + (lane&7) + (lane&8), khalf = lane>>4
    const int a_row  = m0 + (lane & 7) + (lane & 8);
    const int a_ksel = (lane >> 4) & 1;       // 0: k0, 1: k0+8
    unsigned int aaddr_h = smem_u32(Ah + a_row * APITCH + a_ksel * 8);
    unsigned int aaddr_l = smem_u32(Al + a_row * APITCH + a_ksel * 8);
    // B ldmatrix.trans lane addressing (x4 on k-major W):
    // tile = lane>>3 : {k0,n0},{k0,n8},{k8,n0},{k8,n8}
    const int b_krow = ((lane >> 4) & 1) * 8 + (lane & 7);
    const int b_nsel = (lane >> 3) & 1;
    unsigned int baddr_h = smem_u32(Wh + b_krow * APITCH + b_nsel * 8);
    unsigned int baddr_l = smem_u32(Wl + b_krow * APITCH + b_nsel * 8);

#pragma unroll
    for (int ks = 0; ks < 8; ks++) {
        const unsigned int koffA = ks * 32;                // 16 bf16 = 32 bytes along row
        const unsigned int koffB = ks * 16 * (APITCH * 2); // 16 k-rows
        unsigned int ah0, ah1, ah2, ah3, al0, al1, al2, al3;
        ldsm_x4(aaddr_h + koffA, ah0, ah1, ah2, ah3);
        ldsm_x4(aaddr_l + koffA, al0, al1, al2, al3);
#pragma unroll
        for (int ntp = 0; ntp < 8; ntp++) {
            unsigned int noff = ntp * 32;                  // 16 cols = 32 bytes
            unsigned int bh0, bh1, bh2, bh3, bl0, bl1, bl2, bl3;
            ldsm_x4t(baddr_h + koffB + noff, bh0, bh1, bh2, bh3);
            ldsm_x4t(baddr_l + koffB + noff, bl0, bl1, bl2, bl3);
            // ntile 2*ntp   : B regs {bh0, bh2}
            mma16816(acc[ntp * 2],     ah0, ah1, ah2, ah3, bh0, bh2);
            mma16816(acc[ntp * 2],     al0, al1, al2, al3, bh0, bh2);
            mma16816(acc[ntp * 2],     ah0, ah1, ah2, ah3, bl0, bl2);
            // ntile 2*ntp+1 : B regs {bh1, bh3}
            mma16816(acc[ntp * 2 + 1], ah0, ah1, ah2, ah3, bh1, bh3);
            mma16816(acc[ntp * 2 + 1], al0, al1, al2, al3, bh1, bh3);
            mma16816(acc[ntp * 2 + 1], ah0, ah1, ah2, ah3, bl1, bl3);
        }
    }

    // ---- epilogue ----
    const int tr = lane >> 2;
    const int tc = (lane & 3) * 2;
    const int r_lo = row0 + m0 + tr;
    const int r_hi = r_lo + 8;
#pragma unroll
    for (int nt = 0; nt < 16; nt++) {
        int col = nt * 8 + tc;
        if (r_lo < M)
            *reinterpret_cast<float2*>(C + (size_t)r_lo * 128 + col) =
                make_float2(acc[nt][0], acc[nt][1]);
        if (r_hi < M)
            *reinterpret_cast<float2*>(C + (size_t)r_hi * 128 + col) =
                make_float2(acc[nt][2], acc[nt][3]);
    }
}

// ---------------------------------------------------------------------------
// CSR SpMM + fused epilogue. One warp per destination row.
//   agg = sum_s nodef[s,:] * os[s];  rst = leaky_relu(agg * is[d], 0.5)
//   emb[d,:] = rst;  acc_out[d,:] += rst / max(||rst||, 1e-12)
// ---------------------------------------------------------------------------
__global__ __launch_bounds__(256)
void k_spmm(const float* __restrict__ nodef, const int* __restrict__ rp,
            const int* __restrict__ col, const float* __restrict__ osc,
            const float* __restrict__ isc,
            float* __restrict__ emb, float* __restrict__ acc_out, int n) {
    int w = (blockIdx.x * blockDim.x + threadIdx.x) >> 5;
    int lane = threadIdx.x & 31;
    if (w >= n) return;
    int b = rp[w], e = rp[w + 1];

    float4 a = make_float4(0.f, 0.f, 0.f, 0.f);
    int j = b;
    for (; j + 4 <= e; j += 4) {
        int s0 = col[j], s1 = col[j + 1], s2 = col[j + 2], s3 = col[j + 3];
        float o0 = __ldg(osc + s0), o1 = __ldg(osc + s1);
        float o2 = __ldg(osc + s2), o3 = __ldg(osc + s3);
        float4 v0 = __ldg(reinterpret_cast<const float4*>(nodef + (size_t)s0 * HID) + lane);
        float4 v1 = __ldg(reinterpret_cast<const float4*>(nodef + (size_t)s1 * HID) + lane);
        float4 v2 = __ldg(reinterpret_cast<const float4*>(nodef + (size_t)s2 * HID) + lane);
        float4 v3 = __ldg(reinterpret_cast<const float4*>(nodef + (size_t)s3 * HID) + lane);
        a.x = fmaf(v0.x, o0, fmaf(v1.x, o1, fmaf(v2.x, o2, fmaf(v3.x, o3, a.x))));
        a.y = fmaf(v0.y, o0, fmaf(v1.y, o1, fmaf(v2.y, o2, fmaf(v3.y, o3, a.y))));
        a.z = fmaf(v0.z, o0, fmaf(v1.z, o1, fmaf(v2.z, o2, fmaf(v3.z, o3, a.z))));
        a.w = fmaf(v0.w, o0, fmaf(v1.w, o1, fmaf(v2.w, o2, fmaf(v3.w, o3, a.w))));
    }
    for (; j < e; j++) {
        int s = col[j];
        float o = __ldg(osc + s);
        float4 v = __ldg(reinterpret_cast<const float4*>(nodef + (size_t)s * HID) + lane);
        a.x = fmaf(v.x, o, a.x); a.y = fmaf(v.y, o, a.y);
        a.z = fmaf(v.z, o, a.z); a.w = fmaf(v.w, o, a.w);
    }

    float sc = isc[w];
    a.x *= sc; a.y *= sc; a.z *= sc; a.w *= sc;
    a.x = a.x >= 0.f ? a.x : 0.5f * a.x;
    a.y = a.y >= 0.f ? a.y : 0.5f * a.y;
    a.z = a.z >= 0.f ? a.z : 0.5f * a.z;
    a.w = a.w >= 0.f ? a.w : 0.5f * a.w;

    reinterpret_cast<float4*>(emb + (size_t)w * HID)[lane] = a;

    float sq = a.x * a.x + a.y * a.y + a.z * a.z + a.w * a.w;
#pragma unroll
    for (int o = 16; o > 0; o >>= 1)
        sq += __shfl_xor_sync(0xffffffffu, sq, o);
    float inv = 1.0f / fmaxf(sqrtf(sq), 1e-12f);

    float4* op = reinterpret_cast<float4*>(acc_out + (size_t)w * HID) + lane;
    float4 o = *op;
    o.x += a.x * inv; o.y += a.y * inv; o.z += a.z * inv; o.w += a.w * inv;
    *op = o;
}

// ---------------------------------------------------------------------------
// Launch
// ---------------------------------------------------------------------------
extern "C" void kernel_launch(void* const* d_in, const int* in_sizes, int n_in,
                              void* d_out, int out_size) {
    (void)in_sizes; (void)n_in; (void)out_size;
    const float* user_emb = (const float*)d_in[0];
    const float* item_emb = (const float*)d_in[1];
    const float* ui_u_w   = (const float*)d_in[2];
    const float* ui_v_w   = (const float*)d_in[3];
    const float* uu_u_w   = (const float*)d_in[4];
    const int*   src_ui   = (const int*)d_in[5];
    const int*   dst_ui   = (const int*)d_in[6];
    const int*   src_uu   = (const int*)d_in[7];
    const int*   dst_uu   = (const int*)d_in[8];
    float* out = (float*)d_out;

    void* p;
    float *emb, *nodef, *os_ui, *is_ui, *os_uu, *is_uu;
    int *rp_ui, *cur_ui, *col_ui, *rp_uu, *cur_uu, *col_uu;
    int *do_ui, *di_ui, *do_uu, *di_uu, *bsum;
    cudaGetSymbolAddress(&p, g_emb);    emb    = (float*)p;
    cudaGetSymbolAddress(&p, g_nodef);  nodef  = (float*)p;
    cudaGetSymbolAddress(&p, g_os_ui);  os_ui  = (float*)p;
    cudaGetSymbolAddress(&p, g_is_ui);  is_ui  = (float*)p;
    cudaGetSymbolAddress(&p, g_os_uu);  os_uu  = (float*)p;
    cudaGetSymbolAddress(&p, g_is_uu);  is_uu  = (float*)p;
    cudaGetSymbolAddress(&p, g_rp_ui);  rp_ui  = (int*)p;
    cudaGetSymbolAddress(&p, g_cur_ui); cur_ui = (int*)p;
    cudaGetSymbolAddress(&p, g_col_ui); col_ui = (int*)p;
    cudaGetSymbolAddress(&p, g_rp_uu);  rp_uu  = (int*)p;
    cudaGetSymbolAddress(&p, g_cur_uu); cur_uu = (int*)p;
    cudaGetSymbolAddress(&p, g_col_uu); col_uu = (int*)p;
    cudaGetSymbolAddress(&p, g_do_ui);  do_ui  = (int*)p;
    cudaGetSymbolAddress(&p, g_di_ui);  di_ui  = (int*)p;
    cudaGetSymbolAddress(&p, g_do_uu);  do_uu  = (int*)p;
    cudaGetSymbolAddress(&p, g_di_uu);  di_uu  = (int*)p;
    cudaGetSymbolAddress(&p, g_bsum);   bsum   = (int*)p;

    cudaFuncSetAttribute(k_gemm, cudaFuncAttributeMaxDynamicSharedMemorySize, GEMM_SMEM);

    cudaStream_t st = 0;
    const int U4 = NUSER * HID / 4;
    const int I4 = NITEM * HID / 4;
    const int GU = (NUSER + 127) / 128;   // 782
    const int GI = (NITEM + 127) / 128;   // 1563

    // ---- launches 1-5: init copies (emb + out accumulators) ----
    k_copy4<<<(U4 + 255) / 256, 256, 0, st>>>(emb, user_emb, U4);
    k_copy4<<<(I4 + 255) / 256, 256, 0, st>>>(emb + (size_t)NUSER * HID, item_emb, I4);
    k_copy4<<<(U4 + 255) / 256, 256, 0, st>>>(out, user_emb, U4);
    k_copy4<<<(I4 + 255) / 256, 256, 0, st>>>(out + (size_t)NUSER * HID, item_emb, I4);
    k_copy4<<<(U4 + 255) / 256, 256, 0, st>>>(out + (size_t)NALL * HID, user_emb, U4);

    // ---- launches 6-7: layer-0 GEMMs (profiled by ncu -s 5 -c 1) ----
    k_gemm<<<GU, 256, GEMM_SMEM, st>>>(emb, ui_u_w, nodef, NUSER);
    k_gemm<<<GI, 256, GEMM_SMEM, st>>>(emb + (size_t)NUSER * HID, ui_v_w,
                                       nodef + (size_t)NUSER * HID, NITEM);

    // ---- graph preprocessing (needed before first SpMM) ----
    cudaMemsetAsync(do_ui, 0, NALL  * sizeof(int), st);
    cudaMemsetAsync(di_ui, 0, NALL  * sizeof(int), st);
    cudaMemsetAsync(do_uu, 0, NUSER * sizeof(int), st);
    cudaMemsetAsync(di_uu, 0, NUSER * sizeof(int), st);
    k_hist<<<(EUI + 255) / 256, 256, 0, st>>>(src_ui, dst_ui, EUI, do_ui, di_ui);
    k_hist<<<(EUU + 255) / 256, 256, 0, st>>>(src_uu, dst_uu, EUU, do_uu, di_uu);
    {
        int nb = (NALL + 1 + 1023) / 1024;
        k_scan_block<<<nb, 1024, 0, st>>>(di_ui, NALL, rp_ui, bsum);
        k_scan_sums<<<1, 512, 0, st>>>(bsum, nb);
        k_add<<<(NALL + 1 + 255) / 256, 256, 0, st>>>(rp_ui, cur_ui, bsum, NALL + 1);
    }
    {
        int nb = (NUSER + 1 + 1023) / 1024;
        k_scan_block<<<nb, 1024, 0, st>>>(di_uu, NUSER, rp_uu, bsum);
        k_scan_sums<<<1, 512, 0, st>>>(bsum, nb);
        k_add<<<(NUSER + 1 + 255) / 256, 256, 0, st>>>(rp_uu, cur_uu, bsum, NUSER + 1);
    }
    k_scales<<<(NALL  + 255) / 256, 256, 0, st>>>(do_ui, di_ui, os_ui, is_ui, NALL);
    k_scales<<<(NUSER + 255) / 256, 256, 0, st>>>(do_uu, di_uu, os_uu, is_uu, NUSER);
    k_scatter<<<(EUI + 255) / 256, 256, 0, st>>>(src_ui, dst_ui, EUI, cur_ui, col_ui);
    k_scatter<<<(EUU + 255) / 256, 256, 0, st>>>(src_uu, dst_uu, EUU, cur_uu, col_uu);
    k_sortrows<<<(NALL  + 255) / 256, 256, 0, st>>>(rp_ui, col_ui, NALL);
    k_sortrows<<<(NUSER + 255) / 256, 256, 0, st>>>(rp_uu, col_uu, NUSER);

    // ---- user-item propagation ----
    k_spmm<<<(NALL + 7) / 8, 256, 0, st>>>(nodef, rp_ui, col_ui, os_ui, is_ui,
                                           emb, out, NALL);
    for (int i = 1; i < LUI; i++) {
        k_gemm<<<GU, 256, GEMM_SMEM, st>>>(emb, ui_u_w + (size_t)i * HID * HID,
                                           nodef, NUSER);
        k_gemm<<<GI, 256, GEMM_SMEM, st>>>(emb + (size_t)NUSER * HID,
                                           ui_v_w + (size_t)i * HID * HID,
                                           nodef + (size_t)NUSER * HID, NITEM);
        k_spmm<<<(NALL + 7) / 8, 256, 0, st>>>(nodef, rp_ui, col_ui, os_ui, is_ui,
                                               emb, out, NALL);
    }

    // ---- user-user (social) propagation ----
    k_copy4<<<(U4 + 255) / 256, 256, 0, st>>>(emb, user_emb, U4);
    for (int i = 0; i < LUU; i++) {
        k_gemm<<<GU, 256, GEMM_SMEM, st>>>(emb, uu_u_w + (size_t)i * HID * HID,
                                           nodef, NUSER);
        k_spmm<<<(NUSER + 7) / 8, 256, 0, st>>>(nodef, rp_uu, col_uu, os_uu, is_uu,
                                                emb, out + (size_t)NALL * HID, NUSER);
    }
}

// round 9
// speedup vs baseline: 1.5266x; 1.1040x over previous
#include <cuda_runtime.h>
#include <cuda_bf16.h>
#include <cstdint>
#include <stdint.h>
#include <math.h>

// ---------------------------------------------------------------------------
// Problem constants
// ---------------------------------------------------------------------------
#define NUSER 100000
#define NITEM 200000
#define NALL  300000
#define HID   128
#define EUI   2000000
#define EUU   800000
#define LUI   3
#define LUU   2

#define APITCH 136   // bf16 elements per SMEM row (272B: conflict-free ldmatrix)
// smem: A hi/lo (64 rows) + W hi/lo (128 rows), bf16
#define GEMM_SMEM ((2 * 64 + 2 * 128) * APITCH * 2)   // 104448 B -> 2 CTAs/SM

// ---------------------------------------------------------------------------
// Scratch (device globals — no allocation allowed)
// ---------------------------------------------------------------------------
__device__ float g_emb  [(size_t)NALL * HID];
__device__ float g_nodef[(size_t)NALL * HID];

__device__ int   g_rp_ui [NALL + 1];
__device__ int   g_cur_ui[NALL];
__device__ int   g_col_ui[EUI];
__device__ int   g_rp_uu [NUSER + 1];
__device__ int   g_cur_uu[NUSER];
__device__ int   g_col_uu[EUU];

__device__ int   g_do_ui[NALL];
__device__ int   g_di_ui[NALL];
__device__ int   g_do_uu[NUSER];
__device__ int   g_di_uu[NUSER];

__device__ float g_os_ui[NALL];
__device__ float g_is_ui[NALL];
__device__ float g_os_uu[NUSER];
__device__ float g_is_uu[NUSER];

__device__ int   g_bsum[512];

// ---------------------------------------------------------------------------
// Preprocessing kernels
// ---------------------------------------------------------------------------
__global__ void k_hist(const int* __restrict__ src, const int* __restrict__ dst,
                       int E, int* __restrict__ dsrc, int* __restrict__ ddst) {
    int i = blockIdx.x * blockDim.x + threadIdx.x;
    if (i < E) {
        atomicAdd(&dsrc[src[i]], 1);
        atomicAdd(&ddst[dst[i]], 1);
    }
}

__global__ void k_scan_block(const int* __restrict__ deg, int n,
                             int* __restrict__ out, int* __restrict__ bsum) {
    __shared__ int s[1024];
    int tid = threadIdx.x;
    int i = blockIdx.x * 1024 + tid;
    int v = (i < n) ? deg[i] : 0;
    s[tid] = v;
    __syncthreads();
    for (int off = 1; off < 1024; off <<= 1) {
        int t = (tid >= off) ? s[tid - off] : 0;
        __syncthreads();
        s[tid] += t;
        __syncthreads();
    }
    if (i <= n) out[i] = s[tid] - v;
    if (tid == 1023) bsum[blockIdx.x] = s[1023];
}

__global__ void k_scan_sums(int* __restrict__ bs, int nb) {
    __shared__ int s[512];
    int tid = threadIdx.x;
    int v = (tid < nb) ? bs[tid] : 0;
    s[tid] = v;
    __syncthreads();
    for (int off = 1; off < 512; off <<= 1) {
        int t = (tid >= off) ? s[tid - off] : 0;
        __syncthreads();
        s[tid] += t;
        __syncthreads();
    }
    if (tid < nb) bs[tid] = s[tid] - v;
}

__global__ void k_add(int* __restrict__ rp, int* __restrict__ cur,
                      const int* __restrict__ bs, int total) {
    int i = blockIdx.x * blockDim.x + threadIdx.x;
    if (i < total) {
        int v = rp[i] + bs[i >> 10];
        rp[i] = v;
        if (i < total - 1) cur[i] = v;
    }
}

__global__ void k_scales(const int* __restrict__ dout, const int* __restrict__ din,
                         float* __restrict__ os, float* __restrict__ is_, int n) {
    int i = blockIdx.x * blockDim.x + threadIdx.x;
    if (i < n) {
        os[i]  = rsqrtf(fmaxf((float)dout[i], 1.0f));
        is_[i] = rsqrtf(fmaxf((float)din[i],  1.0f));
    }
}

__global__ void k_scatter(const int* __restrict__ src, const int* __restrict__ dst,
                          int E, int* __restrict__ cur, int* __restrict__ col) {
    int i = blockIdx.x * blockDim.x + threadIdx.x;
    if (i < E) {
        int pos = atomicAdd(&cur[dst[i]], 1);
        col[pos] = src[i];
    }
}

__global__ void k_sortrows(const int* __restrict__ rp, int* __restrict__ col, int n) {
    int i = blockIdx.x * blockDim.x + threadIdx.x;
    if (i >= n) return;
    int b = rp[i], e = rp[i + 1];
    for (int j = b + 1; j < e; j++) {
        int key = col[j];
        int k = j - 1;
        while (k >= b && col[k] > key) { col[k + 1] = col[k]; k--; }
        col[k + 1] = key;
    }
}

// ---------------------------------------------------------------------------
// Tensor-core GEMM: C = A @ W  (A:[M,128] fp32, W:[128,128] fp32 row-major)
// bf16 2-term split (Ah*Wh + Al*Wh + Ah*Wl) via mma.sync.m16n8k16.
// One block = 64 rows x 128 cols (4 warps), K=128 in one SMEM slab, 2 CTA/SM.
// ---------------------------------------------------------------------------
__device__ __forceinline__ void cvt_split4(float4 v,
        __nv_bfloat162& h01, __nv_bfloat162& h23,
        __nv_bfloat162& l01, __nv_bfloat162& l23) {
    __nv_bfloat16 hx = __float2bfloat16_rn(v.x);
    __nv_bfloat16 hy = __float2bfloat16_rn(v.y);
    __nv_bfloat16 hz = __float2bfloat16_rn(v.z);
    __nv_bfloat16 hw = __float2bfloat16_rn(v.w);
    __nv_bfloat16 lx = __float2bfloat16_rn(v.x - __bfloat162float(hx));
    __nv_bfloat16 ly = __float2bfloat16_rn(v.y - __bfloat162float(hy));
    __nv_bfloat16 lz = __float2bfloat16_rn(v.z - __bfloat162float(hz));
    __nv_bfloat16 lw = __float2bfloat16_rn(v.w - __bfloat162float(hw));
    h01 = __nv_bfloat162(hx, hy); h23 = __nv_bfloat162(hz, hw);
    l01 = __nv_bfloat162(lx, ly); l23 = __nv_bfloat162(lz, lw);
}

__device__ __forceinline__ unsigned int smem_u32(const void* p) {
    return (unsigned int)__cvta_generic_to_shared(p);
}

__device__ __forceinline__ void ldsm_x4(unsigned int addr,
        unsigned int& r0, unsigned int& r1, unsigned int& r2, unsigned int& r3) {
    asm volatile("ldmatrix.sync.aligned.m8n8.x4.shared.b16 {%0,%1,%2,%3}, [%4];"
                 : "=r"(r0), "=r"(r1), "=r"(r2), "=r"(r3) : "r"(addr));
}
__device__ __forceinline__ void ldsm_x4t(unsigned int addr,
        unsigned int& r0, unsigned int& r1, unsigned int& r2, unsigned int& r3) {
    asm volatile("ldmatrix.sync.aligned.m8n8.x4.trans.shared.b16 {%0,%1,%2,%3}, [%4];"
                 : "=r"(r0), "=r"(r1), "=r"(r2), "=r"(r3) : "r"(addr));
}
__device__ __forceinline__ void mma16816(float* c,
        unsigned int a0, unsigned int a1, unsigned int a2, unsigned int a3,
        unsigned int b0, unsigned int b1) {
    asm volatile("mma.sync.aligned.m16n8k16.row.col.f32.bf16.bf16.f32 "
                 "{%0,%1,%2,%3}, {%4,%5,%6,%7}, {%8,%9}, {%0,%1,%2,%3};"
                 : "+f"(c[0]), "+f"(c[1]), "+f"(c[2]), "+f"(c[3])
                 : "r"(a0), "r"(a1), "r"(a2), "r"(a3), "r"(b0), "r"(b1));
}

__global__ __launch_bounds__(128, 2)
void k_gemm(const float* __restrict__ A, const float* __restrict__ W,
            float* __restrict__ C, int M) {
    extern __shared__ __align__(16) unsigned char smem[];
    __nv_bfloat16* Ah = reinterpret_cast<__nv_bfloat16*>(smem);
    __nv_bfloat16* Al = Ah + 64 * APITCH;
    __nv_bfloat16* Wh = Al + 64 * APITCH;
    __nv_bfloat16* Wl = Wh + 128 * APITCH;

    const int tid = threadIdx.x;
    const int row0 = blockIdx.x * 64;

    // ---- stage A (64 rows) as bf16 hi/lo ----
#pragma unroll
    for (int i = 0; i < 16; i++) {
        int idx = tid + i * 128;           // 2048 float4
        int r  = idx >> 5;                 // 0..63
        int c4 = idx & 31;
        float4 va = make_float4(0.f, 0.f, 0.f, 0.f);
        if (row0 + r < M)
            va = *reinterpret_cast<const float4*>(A + (size_t)(row0 + r) * 128 + c4 * 4);
        __nv_bfloat162 h01, h23, l01, l23;
        cvt_split4(va, h01, h23, l01, l23);
        __nv_bfloat162* pa = reinterpret_cast<__nv_bfloat162*>(Ah + r * APITCH + c4 * 4);
        pa[0] = h01; pa[1] = h23;
        __nv_bfloat162* pal = reinterpret_cast<__nv_bfloat162*>(Al + r * APITCH + c4 * 4);
        pal[0] = l01; pal[1] = l23;
    }
    // ---- stage W (128 k-rows) as bf16 hi/lo ----
#pragma unroll
    for (int i = 0; i < 32; i++) {
        int idx = tid + i * 128;           // 4096 float4
        int r  = idx >> 5;                 // k row 0..127
        int c4 = idx & 31;
        float4 vw = *reinterpret_cast<const float4*>(W + (size_t)r * 128 + c4 * 4);
        __nv_bfloat162 h01, h23, l01, l23;
        cvt_split4(vw, h01, h23, l01, l23);
        __nv_bfloat162* pw = reinterpret_cast<__nv_bfloat162*>(Wh + r * APITCH + c4 * 4);
        pw[0] = h01; pw[1] = h23;
        __nv_bfloat162* pwl = reinterpret_cast<__nv_bfloat162*>(Wl + r * APITCH + c4 * 4);
        pwl[0] = l01; pwl[1] = l23;
    }
    __syncthreads();

    // ---- compute: warp w owns rows m0..m0+15, full N=128 ----
    const int lane = tid & 31;
    const int w    = tid >> 5;             // 0..3
    const int m0   = w * 16;

    float acc[16][4];
#pragma unroll
    for (int i = 0; i < 16; i++)
#pragma unroll
        for (int j = 0; j < 4; j++) acc[i][j] = 0.0f;

    const int a_row  = m0 + (lane & 7) + (lane & 8);
    const int a_ksel = (lane >> 4) & 1;
    unsigned int aaddr_h = smem_u32(Ah + a_row * APITCH + a_ksel * 8);
    unsigned int aaddr_l = smem_u32(Al + a_row * APITCH + a_ksel * 8);
    const int b_krow = ((lane >> 4) & 1) * 8 + (lane & 7);
    const int b_nsel = (lane >> 3) & 1;
    unsigned int baddr_h = smem_u32(Wh + b_krow * APITCH + b_nsel * 8);
    unsigned int baddr_l = smem_u32(Wl + b_krow * APITCH + b_nsel * 8);

#pragma unroll
    for (int ks = 0; ks < 8; ks++) {
        const unsigned int koffA = ks * 32;
        const unsigned int koffB = ks * 16 * (APITCH * 2);
        unsigned int ah0, ah1, ah2, ah3, al0, al1, al2, al3;
        ldsm_x4(aaddr_h + koffA, ah0, ah1, ah2, ah3);
        ldsm_x4(aaddr_l + koffA, al0, al1, al2, al3);
#pragma unroll
        for (int ntp = 0; ntp < 8; ntp++) {
            unsigned int noff = ntp * 32;
            unsigned int bh0, bh1, bh2, bh3, bl0, bl1, bl2, bl3;
            ldsm_x4t(baddr_h + koffB + noff, bh0, bh1, bh2, bh3);
            ldsm_x4t(baddr_l + koffB + noff, bl0, bl1, bl2, bl3);
            mma16816(acc[ntp * 2],     ah0, ah1, ah2, ah3, bh0, bh2);
            mma16816(acc[ntp * 2],     al0, al1, al2, al3, bh0, bh2);
            mma16816(acc[ntp * 2],     ah0, ah1, ah2, ah3, bl0, bl2);
            mma16816(acc[ntp * 2 + 1], ah0, ah1, ah2, ah3, bh1, bh3);
            mma16816(acc[ntp * 2 + 1], al0, al1, al2, al3, bh1, bh3);
            mma16816(acc[ntp * 2 + 1], ah0, ah1, ah2, ah3, bl1, bl3);
        }
    }

    // ---- epilogue ----
    const int tr = lane >> 2;
    const int tc = (lane & 3) * 2;
    const int r_lo = row0 + m0 + tr;
    const int r_hi = r_lo + 8;
#pragma unroll
    for (int nt = 0; nt < 16; nt++) {
        int col = nt * 8 + tc;
        if (r_lo < M)
            *reinterpret_cast<float2*>(C + (size_t)r_lo * 128 + col) =
                make_float2(acc[nt][0], acc[nt][1]);
        if (r_hi < M)
            *reinterpret_cast<float2*>(C + (size_t)r_hi * 128 + col) =
                make_float2(acc[nt][2], acc[nt][3]);
    }
}

// ---------------------------------------------------------------------------
// CSR SpMM + fused epilogue. One warp per destination row.
//   agg = sum_s nodef[s,:] * os[s];  rst = leaky_relu(agg * is[d], 0.5)
//   emb[d,:] = rst
//   first!=0: acc_out[d,:] = init[d,:] + rst/||rst||   (init = A/B split at thresh)
//   first==0: acc_out[d,:] += rst/||rst||
// ---------------------------------------------------------------------------
__global__ __launch_bounds__(256)
void k_spmm(const float* __restrict__ nodef, const int* __restrict__ rp,
            const int* __restrict__ col, const float* __restrict__ osc,
            const float* __restrict__ isc,
            float* __restrict__ emb, float* __restrict__ acc_out, int n,
            int first, const float* __restrict__ initA,
            const float* __restrict__ initB, int thresh) {
    int w = (blockIdx.x * blockDim.x + threadIdx.x) >> 5;
    int lane = threadIdx.x & 31;
    if (w >= n) return;
    int b = rp[w], e = rp[w + 1];

    float4 a = make_float4(0.f, 0.f, 0.f, 0.f);
    int j = b;
    for (; j + 4 <= e; j += 4) {
        int s0 = col[j], s1 = col[j + 1], s2 = col[j + 2], s3 = col[j + 3];
        float o0 = __ldg(osc + s0), o1 = __ldg(osc + s1);
        float o2 = __ldg(osc + s2), o3 = __ldg(osc + s3);
        float4 v0 = __ldg(reinterpret_cast<const float4*>(nodef + (size_t)s0 * HID) + lane);
        float4 v1 = __ldg(reinterpret_cast<const float4*>(nodef + (size_t)s1 * HID) + lane);
        float4 v2 = __ldg(reinterpret_cast<const float4*>(nodef + (size_t)s2 * HID) + lane);
        float4 v3 = __ldg(reinterpret_cast<const float4*>(nodef + (size_t)s3 * HID) + lane);
        a.x = fmaf(v0.x, o0, fmaf(v1.x, o1, fmaf(v2.x, o2, fmaf(v3.x, o3, a.x))));
        a.y = fmaf(v0.y, o0, fmaf(v1.y, o1, fmaf(v2.y, o2, fmaf(v3.y, o3, a.y))));
        a.z = fmaf(v0.z, o0, fmaf(v1.z, o1, fmaf(v2.z, o2, fmaf(v3.z, o3, a.z))));
        a.w = fmaf(v0.w, o0, fmaf(v1.w, o1, fmaf(v2.w, o2, fmaf(v3.w, o3, a.w))));
    }
    for (; j < e; j++) {
        int s = col[j];
        float o = __ldg(osc + s);
        float4 v = __ldg(reinterpret_cast<const float4*>(nodef + (size_t)s * HID) + lane);
        a.x = fmaf(v.x, o, a.x); a.y = fmaf(v.y, o, a.y);
        a.z = fmaf(v.z, o, a.z); a.w = fmaf(v.w, o, a.w);
    }

    float sc = isc[w];
    a.x *= sc; a.y *= sc; a.z *= sc; a.w *= sc;
    a.x = a.x >= 0.f ? a.x : 0.5f * a.x;
    a.y = a.y >= 0.f ? a.y : 0.5f * a.y;
    a.z = a.z >= 0.f ? a.z : 0.5f * a.z;
    a.w = a.w >= 0.f ? a.w : 0.5f * a.w;

    reinterpret_cast<float4*>(emb + (size_t)w * HID)[lane] = a;

    float sq = a.x * a.x + a.y * a.y + a.z * a.z + a.w * a.w;
#pragma unroll
    for (int o = 16; o > 0; o >>= 1)
        sq += __shfl_xor_sync(0xffffffffu, sq, o);
    float inv = 1.0f / fmaxf(sqrtf(sq), 1e-12f);

    float4* op = reinterpret_cast<float4*>(acc_out + (size_t)w * HID) + lane;
    float4 o;
    if (first) {
        const float* ip = (w < thresh) ? (initA + (size_t)w * HID)
                                       : (initB + (size_t)(w - thresh) * HID);
        o = __ldg(reinterpret_cast<const float4*>(ip) + lane);
    } else {
        o = *op;
    }
    o.x += a.x * inv; o.y += a.y * inv; o.z += a.z * inv; o.w += a.w * inv;
    *op = o;
}

// ---------------------------------------------------------------------------
// Launch
// ---------------------------------------------------------------------------
extern "C" void kernel_launch(void* const* d_in, const int* in_sizes, int n_in,
                              void* d_out, int out_size) {
    (void)in_sizes; (void)n_in; (void)out_size;
    const float* user_emb = (const float*)d_in[0];
    const float* item_emb = (const float*)d_in[1];
    const float* ui_u_w   = (const float*)d_in[2];
    const float* ui_v_w   = (const float*)d_in[3];
    const float* uu_u_w   = (const float*)d_in[4];
    const int*   src_ui   = (const int*)d_in[5];
    const int*   dst_ui   = (const int*)d_in[6];
    const int*   src_uu   = (const int*)d_in[7];
    const int*   dst_uu   = (const int*)d_in[8];
    float* out = (float*)d_out;

    void* p;
    float *emb, *nodef, *os_ui, *is_ui, *os_uu, *is_uu;
    int *rp_ui, *cur_ui, *col_ui, *rp_uu, *cur_uu, *col_uu;
    int *do_ui, *di_ui, *do_uu, *di_uu, *bsum;
    cudaGetSymbolAddress(&p, g_emb);    emb    = (float*)p;
    cudaGetSymbolAddress(&p, g_nodef);  nodef  = (float*)p;
    cudaGetSymbolAddress(&p, g_os_ui);  os_ui  = (float*)p;
    cudaGetSymbolAddress(&p, g_is_ui);  is_ui  = (float*)p;
    cudaGetSymbolAddress(&p, g_os_uu);  os_uu  = (float*)p;
    cudaGetSymbolAddress(&p, g_is_uu);  is_uu  = (float*)p;
    cudaGetSymbolAddress(&p, g_rp_ui);  rp_ui  = (int*)p;
    cudaGetSymbolAddress(&p, g_cur_ui); cur_ui = (int*)p;
    cudaGetSymbolAddress(&p, g_col_ui); col_ui = (int*)p;
    cudaGetSymbolAddress(&p, g_rp_uu);  rp_uu  = (int*)p;
    cudaGetSymbolAddress(&p, g_cur_uu); cur_uu = (int*)p;
    cudaGetSymbolAddress(&p, g_col_uu); col_uu = (int*)p;
    cudaGetSymbolAddress(&p, g_do_ui);  do_ui  = (int*)p;
    cudaGetSymbolAddress(&p, g_di_ui);  di_ui  = (int*)p;
    cudaGetSymbolAddress(&p, g_do_uu);  do_uu  = (int*)p;
    cudaGetSymbolAddress(&p, g_di_uu);  di_uu  = (int*)p;
    cudaGetSymbolAddress(&p, g_bsum);   bsum   = (int*)p;

    cudaFuncSetAttribute(k_gemm, cudaFuncAttributeMaxDynamicSharedMemorySize, GEMM_SMEM);

    cudaStream_t st = 0;
    const int GU = (NUSER + 63) / 64;   // 1563
    const int GI = (NITEM + 63) / 64;   // 3125

    // ---- layer-0 GEMMs read inputs directly (no emb copy needed) ----
    k_gemm<<<GU, 128, GEMM_SMEM, st>>>(user_emb, ui_u_w, nodef, NUSER);
    k_gemm<<<GI, 128, GEMM_SMEM, st>>>(item_emb, ui_v_w,
                                       nodef + (size_t)NUSER * HID, NITEM);

    // ---- graph preprocessing ----
    cudaMemsetAsync(do_ui, 0, NALL  * sizeof(int), st);
    cudaMemsetAsync(di_ui, 0, NALL  * sizeof(int), st);
    cudaMemsetAsync(do_uu, 0, NUSER * sizeof(int), st);
    cudaMemsetAsync(di_uu, 0, NUSER * sizeof(int), st);
    k_hist<<<(EUI + 255) / 256, 256, 0, st>>>(src_ui, dst_ui, EUI, do_ui, di_ui);
    k_hist<<<(EUU + 255) / 256, 256, 0, st>>>(src_uu, dst_uu, EUU, do_uu, di_uu);
    {
        int nb = (NALL + 1 + 1023) / 1024;
        k_scan_block<<<nb, 1024, 0, st>>>(di_ui, NALL, rp_ui, bsum);
        k_scan_sums<<<1, 512, 0, st>>>(bsum, nb);
        k_add<<<(NALL + 1 + 255) / 256, 256, 0, st>>>(rp_ui, cur_ui, bsum, NALL + 1);
    }
    {
        int nb = (NUSER + 1 + 1023) / 1024;
        k_scan_block<<<nb, 1024, 0, st>>>(di_uu, NUSER, rp_uu, bsum);
        k_scan_sums<<<1, 512, 0, st>>>(bsum, nb);
        k_add<<<(NUSER + 1 + 255) / 256, 256, 0, st>>>(rp_uu, cur_uu, bsum, NUSER + 1);
    }
    k_scales<<<(NALL  + 255) / 256, 256, 0, st>>>(do_ui, di_ui, os_ui, is_ui, NALL);
    k_scales<<<(NUSER + 255) / 256, 256, 0, st>>>(do_uu, di_uu, os_uu, is_uu, NUSER);
    k_scatter<<<(EUI + 255) / 256, 256, 0, st>>>(src_ui, dst_ui, EUI, cur_ui, col_ui);
    k_scatter<<<(EUU + 255) / 256, 256, 0, st>>>(src_uu, dst_uu, EUU, cur_uu, col_uu);
    k_sortrows<<<(NALL  + 255) / 256, 256, 0, st>>>(rp_ui, col_ui, NALL);
    k_sortrows<<<(NUSER + 255) / 256, 256, 0, st>>>(rp_uu, col_uu, NUSER);

    // ---- user-item propagation (out init fused into first spmm) ----
    k_spmm<<<(NALL + 7) / 8, 256, 0, st>>>(nodef, rp_ui, col_ui, os_ui, is_ui,
                                           emb, out, NALL,
                                           1, user_emb, item_emb, NUSER);
    for (int i = 1; i < LUI; i++) {
        k_gemm<<<GU, 128, GEMM_SMEM, st>>>(emb, ui_u_w + (size_t)i * HID * HID,
                                           nodef, NUSER);
        k_gemm<<<GI, 128, GEMM_SMEM, st>>>(emb + (size_t)NUSER * HID,
                                           ui_v_w + (size_t)i * HID * HID,
                                           nodef + (size_t)NUSER * HID, NITEM);
        k_spmm<<<(NALL + 7) / 8, 256, 0, st>>>(nodef, rp_ui, col_ui, os_ui, is_ui,
                                               emb, out, NALL,
                                               0, user_emb, item_emb, NUSER);
    }

    // ---- user-user (social) propagation ----
    k_gemm<<<GU, 128, GEMM_SMEM, st>>>(user_emb, uu_u_w, nodef, NUSER);
    k_spmm<<<(NUSER + 7) / 8, 256, 0, st>>>(nodef, rp_uu, col_uu, os_uu, is_uu,
                                            emb, out + (size_t)NALL * HID, NUSER,
                                            1, user_emb, user_emb, NUSER);
    for (int i = 1; i < LUU; i++) {
        k_gemm<<<GU, 128, GEMM_SMEM, st>>>(emb, uu_u_w + (size_t)i * HID * HID,
                                           nodef, NUSER);
        k_spmm<<<(NUSER + 7) / 8, 256, 0, st>>>(nodef, rp_uu, col_uu, os_uu, is_uu,
                                                emb, out + (size_t)NALL * HID, NUSER,
                                                0, user_emb, user_emb, NUSER);
    }
}